// round 10
// baseline (speedup 1.0000x reference)
#include <cuda_runtime.h>
#include <cuda_fp16.h>
#include <cstdint>

#define NN 8192
#define FIN 256
#define FOUT 128
#define GAT_ALPHA 0.2f
#define NW (NN / 32)            // mask words per row = 256
#define NT (NN / 128)           // j-tiles = 64
#define LOG2E 1.4426950408889634f

// ---------------- scratch (allocation-free: __device__ globals) ----------------
__device__ __half    g_Whh[NN * FOUT];    // Wh fp16
__device__ float     g_s[NN];             // Wh @ a[0:128]  (raw)
__device__ float     g_E[2 * NN];         // per-j: (2^{t'}, 2^{0.2 t'}) interleaved
__device__ unsigned  g_bits[NN * NW];     // adj bit-packed, 8 MB
__device__ unsigned  g_tmax_u = 0;        // order-encoded float max of raw t

__device__ __forceinline__ unsigned fenc(float f) {
    int i = __float_as_int(f);
    return (i >= 0) ? ((unsigned)i + 0x80000000u) : (unsigned)(~i);
}
__device__ __forceinline__ float fdec(unsigned u) {
    return (u >= 0x80000000u) ? __int_as_float((int)(u - 0x80000000u))
                              : __int_as_float((int)~u);
}

// ---------------- Kernel 0: bit-pack adjacency (DRAM-roofline) ---------------
__global__ __launch_bounds__(256) void pack_kernel(const int* __restrict__ adj)
{
    const int gw   = (blockIdx.x * blockDim.x + threadIdx.x) >> 5;
    const int lane = threadIdx.x & 31;
    const size_t base = (size_t)gw * 256;
    unsigned myword = 0;
#pragma unroll
    for (int it = 0; it < 8; it++) {
        int v = adj[base + it * 32 + lane];
        unsigned b = __ballot_sync(0xffffffffu, v > 0);
        if (lane == it) myword = b;
    }
    if (lane < 8) g_bits[(size_t)gw * 8 + lane] = myword;
}

// ---------------- Kernel 1: Wh = h @ W (fp32) -> fp16, s, E tables -----------
__global__ __launch_bounds__(256) void wh_kernel(const float* __restrict__ h,
                                                 const float* __restrict__ W,
                                                 const float* __restrict__ a)
{
    __shared__ float hs[64 * 36];
    __shared__ float Ws[32 * 132];

    const int tid = threadIdx.x;
    const int i0  = blockIdx.x * 64;
    const int tx  = tid & 15;
    const int ty  = tid >> 4;

    float acc[4][8];
#pragma unroll
    for (int i = 0; i < 4; i++)
#pragma unroll
        for (int u = 0; u < 8; u++) acc[i][u] = 0.f;

    for (int kt = 0; kt < FIN; kt += 32) {
        __syncthreads();
#pragma unroll
        for (int q = 0; q < 2; q++) {
            int lin = tid + q * 256;
            int r = lin >> 3, c4 = (lin & 7) * 4;
            *(float4*)&hs[r * 36 + c4] =
                *(const float4*)&h[(size_t)(i0 + r) * FIN + kt + c4];
        }
#pragma unroll
        for (int q = 0; q < 4; q++) {
            int lin = tid + q * 256;
            int r = lin >> 5, c4 = (lin & 31) * 4;
            *(float4*)&Ws[r * 132 + c4] =
                *(const float4*)&W[(size_t)(kt + r) * FOUT + c4];
        }
        __syncthreads();
#pragma unroll 4
        for (int k = 0; k < 32; k++) {
            float bv[8];
#pragma unroll
            for (int u = 0; u < 8; u++) bv[u] = Ws[k * 132 + tx * 8 + u];
#pragma unroll
            for (int i = 0; i < 4; i++) {
                float av = hs[(ty * 4 + i) * 36 + k];
#pragma unroll
                for (int u = 0; u < 8; u++) acc[i][u] = fmaf(av, bv[u], acc[i][u]);
            }
        }
    }

    float a1[8], a2[8];
#pragma unroll
    for (int u = 0; u < 8; u++) {
        a1[u] = a[tx * 8 + u];
        a2[u] = a[FOUT + tx * 8 + u];
    }
#pragma unroll
    for (int i = 0; i < 4; i++) {
        int rg = i0 + ty * 4 + i;
        float ps = 0.f, pt = 0.f;
#pragma unroll
        for (int u = 0; u < 8; u++) {
            float v = acc[i][u];
            g_Whh[(size_t)rg * FOUT + tx * 8 + u] = __float2half(v);
            ps = fmaf(v, a1[u], ps);
            pt = fmaf(v, a2[u], pt);
        }
#pragma unroll
        for (int off = 1; off < 16; off <<= 1) {
            ps += __shfl_xor_sync(0xffffffffu, ps, off);
            pt += __shfl_xor_sync(0xffffffffu, pt, off);
        }
        if (tx == 0) {
            g_s[rg] = ps;
            float tp = pt * LOG2E;
            g_E[2 * rg]     = exp2f(tp);               // E1 = 2^{t'}
            g_E[2 * rg + 1] = exp2f(GAT_ALPHA * tp);   // E2 = 2^{0.2 t'}
            atomicMax(&g_tmax_u, fenc(pt));            // idempotent across replays
        }
    }
}

// ---------------- mma helpers ----------------
__device__ __forceinline__ void ldsm4(uint32_t& r0, uint32_t& r1, uint32_t& r2,
                                      uint32_t& r3, uint32_t addr)
{
    asm volatile("ldmatrix.sync.aligned.m8n8.x4.shared.b16 {%0,%1,%2,%3}, [%4];"
                 : "=r"(r0), "=r"(r1), "=r"(r2), "=r"(r3) : "r"(addr));
}
__device__ __forceinline__ void ldsm4t(uint32_t& r0, uint32_t& r1, uint32_t& r2,
                                       uint32_t& r3, uint32_t addr)
{
    asm volatile("ldmatrix.sync.aligned.m8n8.x4.trans.shared.b16 {%0,%1,%2,%3}, [%4];"
                 : "=r"(r0), "=r"(r1), "=r"(r2), "=r"(r3) : "r"(addr));
}
__device__ __forceinline__ void mma16816(float* c, uint32_t a0, uint32_t a1,
                                         uint32_t a2, uint32_t a3,
                                         uint32_t b0, uint32_t b1)
{
    asm volatile(
        "mma.sync.aligned.m16n8k16.row.col.f32.f16.f16.f32 "
        "{%0,%1,%2,%3}, {%4,%5,%6,%7}, {%8,%9}, {%0,%1,%2,%3};"
        : "+f"(c[0]), "+f"(c[1]), "+f"(c[2]), "+f"(c[3])
        : "r"(a0), "r"(a1), "r"(a2), "r"(a3), "r"(b0), "r"(b1));
}
__device__ __forceinline__ void cpa16(uint32_t dst, const void* src) {
    asm volatile("cp.async.cg.shared.global [%0], [%1], 16;" :: "r"(dst), "l"(src));
}

// ---------------- Kernel 2: table-driven fixed-max fused attention -----------
// 32 rows/CTA, 256 CTAs, 2/SM. Hot loop has ZERO MUFU: p = bit ? (E1>Ethr ?
// c1*E1 : c2*E2) : 0 with E tables L1-resident via __ldg, bits prefetched one
// tile ahead in a register. Double-buffered whh (cp.async) + Ps; half-CTA
// barrier between e-phase and MMA.
#define SMEM_BYTES ((2 * 128 * 136 + 2 * 32 * 136) * 2 + 32 * 4)

__global__ __launch_bounds__(256, 2) void attn_kernel(float* __restrict__ out)
{
    extern __shared__ __align__(16) char smem[];
    __half* whh  = (__half*)smem;                  // [2][128*136]
    __half* Ps   = whh + 2 * 128 * 136;            // [2][32*136]
    float*  linv = (float*)(Ps + 2 * 32 * 136);    // [32]

    const int tid  = threadIdx.x;
    const int i0   = blockIdx.x * 32;
    const int lane = tid & 31;
    const int wid  = tid >> 5;
    const int wm   = wid >> 2;     // 0..1 : 16-row slab
    const int wn   = wid & 3;      // 0..3 : 32-col slab
    const int er   = tid >> 3;     // softmax row 0..31
    const int ej   = tid & 7;      // 16-col chunk

    // loop-invariant per-row constants (MUFU only here, outside the loop)
    const float s_r  = g_s[i0 + er];
    const float tmax = fdec(g_tmax_u);
    const float x    = s_r + tmax;
    const float mhat = fmaxf(x, GAT_ALPHA * x);
    const float c1   = exp2f((s_r - mhat) * LOG2E);
    const float c2   = exp2f((GAT_ALPHA * s_r - mhat) * LOG2E);
    const float Ethr = exp2f(-s_r * LOG2E);        // E1 > Ethr  <=>  s+t > 0

    const unsigned* brow = g_bits + (size_t)(i0 + er) * NW + (ej >> 1);

    float l_acc = 0.f;
    float acc[4][4];
#pragma unroll
    for (int nb = 0; nb < 4; nb++)
#pragma unroll
        for (int v = 0; v < 4; v++) acc[nb][v] = 0.f;

    // ---- prefetch tile 0: whh via cp.async, bits word in register ----
#pragma unroll
    for (int q = 0; q < 8; q++) {
        int lin = tid + q * 256;
        int r = lin >> 4, c = (lin & 15) * 8;
        cpa16((uint32_t)__cvta_generic_to_shared(&whh[r * 136 + c]),
              &g_Whh[(size_t)r * FOUT + c]);
    }
    asm volatile("cp.async.commit_group;");
    unsigned bw_cur = brow[0];

    const int kA_row = wm * 16 + (lane & 15);
    const int kB_row = (lane & 7) + 8 * ((lane >> 3) & 1);
    const int kB_col = wn * 32 + 8 * (lane >> 4);

    for (int jt = 0; jt < NT; jt++) {
        const int b = jt & 1;
        __half* whb = whh + b * 128 * 136;
        __half* Psb = Ps + b * 32 * 136;

        asm volatile("cp.async.wait_group 0;");
        __syncthreads();            // whh[b] resident; MMA(jt-1) done everywhere

        // prefetch whh for jt+1 + bits word for jt+1
        unsigned bw_nxt = 0;
        if (jt + 1 < NT) {
            const int j1 = (jt + 1) * 128;
            __half* whn = whh + (b ^ 1) * 128 * 136;
#pragma unroll
            for (int q = 0; q < 8; q++) {
                int lin = tid + q * 256;
                int r = lin >> 4, c = (lin & 15) * 8;
                cpa16((uint32_t)__cvta_generic_to_shared(&whn[r * 136 + c]),
                      &g_Whh[(size_t)(j1 + r) * FOUT + c]);
            }
            bw_nxt = brow[(jt + 1) * 4];
        }
        asm volatile("cp.async.commit_group;");

        // ---- e-phase: table lookup, no MUFU ----
        const unsigned mhalf = (ej & 1) ? (bw_cur >> 16) : (bw_cur & 0xffffu);
        const float4* Ep = (const float4*)g_E + (jt * 128 + ej * 16) / 2;
        uint32_t pk[8];
#pragma unroll
        for (int q = 0; q < 8; q++) {              // 2 j's per q
            float4 e2 = __ldg(&Ep[q]);             // (E1_j0,E2_j0,E1_j1,E2_j1)
            float p0 = (e2.x > Ethr) ? c1 * e2.x : c2 * e2.y;
            float p1 = (e2.z > Ethr) ? c1 * e2.z : c2 * e2.w;
            p0 = ((mhalf >> (2 * q)) & 1u) ? p0 : 0.f;
            p1 = ((mhalf >> (2 * q + 1)) & 1u) ? p1 : 0.f;
            l_acc += p0 + p1;
            ((__half2*)pk)[q] = __floats2half2_rn(p0, p1);
        }
        *(uint4*)&Psb[er * 136 + ej * 16]     = *(uint4*)&pk[0];
        *(uint4*)&Psb[er * 136 + ej * 16 + 8] = *(uint4*)&pk[4];
        bw_cur = bw_nxt;

        // half-CTA barrier: rows 0-15 <-> threads 0-127; rows 16-31 <-> 128-255
        if (wm == 0) asm volatile("bar.sync 1, 128;" ::: "memory");
        else         asm volatile("bar.sync 2, 128;" ::: "memory");

        // ---- MMA: acc += P @ Wh ----
#pragma unroll
        for (int ks = 0; ks < 8; ks++) {
            uint32_t a0, a1, a2, a3;
            uint32_t aaddr = (uint32_t)__cvta_generic_to_shared(
                &Psb[kA_row * 136 + ks * 16 + (lane >> 4) * 8]);
            ldsm4(a0, a1, a2, a3, aaddr);
#pragma unroll
            for (int ng = 0; ng < 2; ng++) {
                const int nb0 = ng * 2;
                const int boff = (ks * 16 + kB_row) * 136 + kB_col + ng * 16;
                uint32_t b0, b1, b2, b3;
                uint32_t baddr = (uint32_t)__cvta_generic_to_shared(&whb[boff]);
                ldsm4t(b0, b1, b2, b3, baddr);
                mma16816(acc[nb0],     a0, a1, a2, a3, b0, b1);
                mma16816(acc[nb0 + 1], a0, a1, a2, a3, b2, b3);
            }
        }
    }

    // ---- final l reduction (8 threads/row, same warp) ----
    l_acc += __shfl_xor_sync(0xffffffffu, l_acc, 1);
    l_acc += __shfl_xor_sync(0xffffffffu, l_acc, 2);
    l_acc += __shfl_xor_sync(0xffffffffu, l_acc, 4);
    __syncthreads();
    if (ej == 0) linv[er] = 1.0f / l_acc;
    __syncthreads();

    // ---- epilogue: normalize, ELU, store ----
    const float li_lo = linv[wm * 16 + (lane >> 2)];
    const float li_hi = linv[wm * 16 + 8 + (lane >> 2)];
    const int rg0 = i0 + wm * 16 + (lane >> 2);
#pragma unroll
    for (int nb = 0; nb < 4; nb++) {
        const int col = wn * 32 + nb * 8 + (lane & 3) * 2;
        float v0 = acc[nb][0] * li_lo, v1 = acc[nb][1] * li_lo;
        float v2 = acc[nb][2] * li_hi, v3 = acc[nb][3] * li_hi;
        v0 = (v0 > 0.f) ? v0 : expm1f(v0);
        v1 = (v1 > 0.f) ? v1 : expm1f(v1);
        v2 = (v2 > 0.f) ? v2 : expm1f(v2);
        v3 = (v3 > 0.f) ? v3 : expm1f(v3);
        out[(size_t)rg0 * FOUT + col]           = v0;
        out[(size_t)rg0 * FOUT + col + 1]       = v1;
        out[(size_t)(rg0 + 8) * FOUT + col]     = v2;
        out[(size_t)(rg0 + 8) * FOUT + col + 1] = v3;
    }
}

// ---------------- launch ----------------
extern "C" void kernel_launch(void* const* d_in, const int* in_sizes, int n_in,
                              void* d_out, int out_size)
{
    const float* h = nullptr;
    const int*   adj = nullptr;
    const float* W = nullptr;
    const float* a = nullptr;
    for (int i = 0; i < n_in; i++) {
        long s = in_sizes[i];
        if (s == (long)NN * FIN)        h   = (const float*)d_in[i];
        else if (s == (long)NN * NN)    adj = (const int*)d_in[i];
        else if (s == (long)FIN * FOUT) W   = (const float*)d_in[i];
        else if (s == 2 * FOUT)         a   = (const float*)d_in[i];
    }
    float* out = (float*)d_out;

    cudaFuncSetAttribute(attn_kernel,
                         cudaFuncAttributeMaxDynamicSharedMemorySize, SMEM_BYTES);

    pack_kernel<<<NN * NN / 2048, 256>>>(adj);
    wh_kernel<<<NN / 64, 256>>>(h, W, a);
    attn_kernel<<<NN / 32, 256, SMEM_BYTES>>>(out);
}

// round 12
// speedup vs baseline: 1.5659x; 1.5659x over previous
#include <cuda_runtime.h>
#include <cuda_fp16.h>
#include <cstdint>

#define NN 8192
#define FIN 256
#define FOUT 128
#define GAT_ALPHA 0.2f
#define NW (NN / 32)            // mask words per row = 256
#define NTJ 128                 // 64-wide j-tiles
#define JW 64
#define LOG2E 1.4426950408889634f

// ---------------- scratch (allocation-free: __device__ globals) ----------------
__device__ __half    g_Whh[NN * FOUT];    // Wh fp16
__device__ float     g_s[NN];             // Wh @ a[0:128]  (raw)
__device__ float     g_t[NN];             // (Wh @ a[128:256]) * log2(e)
__device__ unsigned  g_bits[NN * NW];     // adj bit-packed, 8 MB
__device__ unsigned  g_tmax_u = 0;        // order-encoded float max of raw t

__device__ __forceinline__ unsigned fenc(float f) {
    int i = __float_as_int(f);
    return (i >= 0) ? ((unsigned)i + 0x80000000u) : (unsigned)(~i);
}
__device__ __forceinline__ float fdec(unsigned u) {
    return (u >= 0x80000000u) ? __int_as_float((int)(u - 0x80000000u))
                              : __int_as_float((int)~u);
}

// ---------------- Kernel 0: bit-pack adjacency (DRAM-roofline) ---------------
__global__ __launch_bounds__(256) void pack_kernel(const int* __restrict__ adj)
{
    const int gw   = (blockIdx.x * blockDim.x + threadIdx.x) >> 5;
    const int lane = threadIdx.x & 31;
    const size_t base = (size_t)gw * 256;
    unsigned myword = 0;
#pragma unroll
    for (int it = 0; it < 8; it++) {
        int v = adj[base + it * 32 + lane];
        unsigned b = __ballot_sync(0xffffffffu, v > 0);
        if (lane == it) myword = b;
    }
    if (lane < 8) g_bits[(size_t)gw * 8 + lane] = myword;
}

// ---------------- Kernel 1: Wh = h @ W (fp32) -> fp16, s, t ------------------
__global__ __launch_bounds__(256) void wh_kernel(const float* __restrict__ h,
                                                 const float* __restrict__ W,
                                                 const float* __restrict__ a)
{
    __shared__ float hs[64 * 36];
    __shared__ float Ws[32 * 132];

    const int tid = threadIdx.x;
    const int i0  = blockIdx.x * 64;
    const int tx  = tid & 15;
    const int ty  = tid >> 4;

    float acc[4][8];
#pragma unroll
    for (int i = 0; i < 4; i++)
#pragma unroll
        for (int u = 0; u < 8; u++) acc[i][u] = 0.f;

    for (int kt = 0; kt < FIN; kt += 32) {
        __syncthreads();
#pragma unroll
        for (int q = 0; q < 2; q++) {
            int lin = tid + q * 256;
            int r = lin >> 3, c4 = (lin & 7) * 4;
            *(float4*)&hs[r * 36 + c4] =
                *(const float4*)&h[(size_t)(i0 + r) * FIN + kt + c4];
        }
#pragma unroll
        for (int q = 0; q < 4; q++) {
            int lin = tid + q * 256;
            int r = lin >> 5, c4 = (lin & 31) * 4;
            *(float4*)&Ws[r * 132 + c4] =
                *(const float4*)&W[(size_t)(kt + r) * FOUT + c4];
        }
        __syncthreads();
#pragma unroll 4
        for (int k = 0; k < 32; k++) {
            float bv[8];
#pragma unroll
            for (int u = 0; u < 8; u++) bv[u] = Ws[k * 132 + tx * 8 + u];
#pragma unroll
            for (int i = 0; i < 4; i++) {
                float av = hs[(ty * 4 + i) * 36 + k];
#pragma unroll
                for (int u = 0; u < 8; u++) acc[i][u] = fmaf(av, bv[u], acc[i][u]);
            }
        }
    }

    float a1[8], a2[8];
#pragma unroll
    for (int u = 0; u < 8; u++) {
        a1[u] = a[tx * 8 + u];
        a2[u] = a[FOUT + tx * 8 + u];
    }
#pragma unroll
    for (int i = 0; i < 4; i++) {
        int rg = i0 + ty * 4 + i;
        float ps = 0.f, pt = 0.f;
#pragma unroll
        for (int u = 0; u < 8; u++) {
            float v = acc[i][u];
            g_Whh[(size_t)rg * FOUT + tx * 8 + u] = __float2half(v);
            ps = fmaf(v, a1[u], ps);
            pt = fmaf(v, a2[u], pt);
        }
#pragma unroll
        for (int off = 1; off < 16; off <<= 1) {
            ps += __shfl_xor_sync(0xffffffffu, ps, off);
            pt += __shfl_xor_sync(0xffffffffu, pt, off);
        }
        if (tx == 0) {
            g_s[rg] = ps;
            g_t[rg] = pt * LOG2E;
            atomicMax(&g_tmax_u, fenc(pt));   // idempotent across replays
        }
    }
}

// ---------------- mma helpers ----------------
__device__ __forceinline__ void ldsm4(uint32_t& r0, uint32_t& r1, uint32_t& r2,
                                      uint32_t& r3, uint32_t addr)
{
    asm volatile("ldmatrix.sync.aligned.m8n8.x4.shared.b16 {%0,%1,%2,%3}, [%4];"
                 : "=r"(r0), "=r"(r1), "=r"(r2), "=r"(r3) : "r"(addr));
}
__device__ __forceinline__ void ldsm4t(uint32_t& r0, uint32_t& r1, uint32_t& r2,
                                       uint32_t& r3, uint32_t addr)
{
    asm volatile("ldmatrix.sync.aligned.m8n8.x4.trans.shared.b16 {%0,%1,%2,%3}, [%4];"
                 : "=r"(r0), "=r"(r1), "=r"(r2), "=r"(r3) : "r"(addr));
}
__device__ __forceinline__ void mma16816(float* c, uint32_t a0, uint32_t a1,
                                         uint32_t a2, uint32_t a3,
                                         uint32_t b0, uint32_t b1)
{
    asm volatile(
        "mma.sync.aligned.m16n8k16.row.col.f32.f16.f16.f32 "
        "{%0,%1,%2,%3}, {%4,%5,%6,%7}, {%8,%9}, {%0,%1,%2,%3};"
        : "+f"(c[0]), "+f"(c[1]), "+f"(c[2]), "+f"(c[3])
        : "r"(a0), "r"(a1), "r"(a2), "r"(a3), "r"(b0), "r"(b1));
}
__device__ __forceinline__ float ex2(float x) {
    float r;
    asm("ex2.approx.f32 %0, %1;" : "=f"(r) : "f"(x));
    return r;
}
__device__ __forceinline__ void cpa16(uint32_t dst, const void* src) {
    asm volatile("cp.async.cg.shared.global [%0], [%1], 16;" :: "r"(dst), "l"(src));
}

// ---------------- Kernel 2: lagged-MMA fused attention -----------------------
// 32 rows/CTA, 256 CTAs, 2/SM. 64-wide j-tiles (128 tiles). Per iteration:
// one __syncthreads, then MMA(jt-1) and e-phase(jt) interleave barrier-free
// (independent buffers). whh/tv triple-buffered via cp.async; Ps double-
// buffered; bits prefetched one tile ahead in a register; fixed per-row max.
#define SMEM_BYTES (3 * JW * 136 * 2 + 2 * 32 * 72 * 2 + 3 * JW * 4 + 32 * 4)

__global__ __launch_bounds__(256, 2) void attn_kernel(float* __restrict__ out)
{
    extern __shared__ __align__(16) char smem[];
    __half* whh  = (__half*)smem;                    // [3][64*136]
    __half* Ps   = whh + 3 * JW * 136;               // [2][32*72]
    float*  tv   = (float*)(Ps + 2 * 32 * 72);       // [3][64]
    float*  linv = tv + 3 * JW;                      // [32]

    const int tid  = threadIdx.x;
    const int i0   = blockIdx.x * 32;
    const int lane = tid & 31;
    const int wid  = tid >> 5;
    const int wm   = wid >> 2;     // 0..1 : 16-row slab
    const int wn   = wid & 3;      // 0..3 : 32-col slab
    const int er   = tid >> 3;     // softmax row 0..31
    const int ej   = tid & 7;      // 8-col chunk of the 64-wide tile

    // loop-invariant per-row softmax constants (fixed max)
    const float s_r  = g_s[i0 + er];
    const float tmax = fdec(g_tmax_u);
    const float x    = s_r + tmax;
    const float mhat = fmaxf(x, GAT_ALPHA * x);
    const float A    = (s_r - mhat) * LOG2E;
    const float B    = (GAT_ALPHA * s_r - mhat) * LOG2E;

    const unsigned* brow = g_bits + (size_t)(i0 + er) * NW;

    float l_acc = 0.f;
    float acc[4][4];
#pragma unroll
    for (int nb = 0; nb < 4; nb++)
#pragma unroll
        for (int v = 0; v < 4; v++) acc[nb][v] = 0.f;

    // ---- prefetch tile 0 into buffer 0 (64 rows x 128 cols = 1024 int4) ----
#pragma unroll
    for (int q = 0; q < 4; q++) {
        int lin = tid + q * 256;
        int r = lin >> 4, c = (lin & 15) * 8;
        cpa16((uint32_t)__cvta_generic_to_shared(&whh[r * 136 + c]),
              &g_Whh[(size_t)r * FOUT + c]);
    }
    if (tid < 16)
        cpa16((uint32_t)__cvta_generic_to_shared(&tv[tid * 4]), &g_t[tid * 4]);
    asm volatile("cp.async.commit_group;");
    unsigned bw_cur = brow[ej >> 2];     // words jt*2 + (ej>>2)

    const int kA_row = wm * 16 + (lane & 15);
    const int kB_row = (lane & 7) + 8 * ((lane >> 3) & 1);
    const int kB_col = wn * 32 + 8 * (lane >> 4);

    int b3 = 0;                          // jt % 3

    for (int jt = 0; jt < NTJ; jt++) {
        const int bn = (b3 == 2) ? 0 : b3 + 1;     // (jt+1) % 3
        const int bp = (b3 == 0) ? 2 : b3 - 1;     // (jt-1) % 3
        const int pb = jt & 1;
        __half* Psb = Ps + pb * 32 * 72;

        asm volatile("cp.async.wait_group 0;");
        __syncthreads();       // whh[b3]/tv[b3] resident; iter jt-1 fully done

        // ---- prefetch tile jt+1 into buffer bn ----
        unsigned bw_nxt = 0;
        if (jt + 1 < NTJ) {
            const int j1 = (jt + 1) * JW;
            __half* whn = whh + bn * JW * 136;
            float*  tvn = tv + bn * JW;
#pragma unroll
            for (int q = 0; q < 4; q++) {
                int lin = tid + q * 256;
                int r = lin >> 4, c = (lin & 15) * 8;
                cpa16((uint32_t)__cvta_generic_to_shared(&whn[r * 136 + c]),
                      &g_Whh[(size_t)(j1 + r) * FOUT + c]);
            }
            if (tid < 16)
                cpa16((uint32_t)__cvta_generic_to_shared(&tvn[tid * 4]),
                      &g_t[j1 + tid * 4]);
            bw_nxt = brow[(jt + 1) * 2 + (ej >> 2)];
        }
        asm volatile("cp.async.commit_group;");

        // ---- MMA(jt-1): acc += P(jt-1) @ Wh(jt-1)  [interleaves with e below]
        if (jt > 0) {
            __half* Psm = Ps + ((jt - 1) & 1) * 32 * 72;
            __half* whm = whh + bp * JW * 136;
#pragma unroll
            for (int ks = 0; ks < 4; ks++) {
                uint32_t a0, a1, a2, a3;
                uint32_t aaddr = (uint32_t)__cvta_generic_to_shared(
                    &Psm[kA_row * 72 + ks * 16 + (lane >> 4) * 8]);
                ldsm4(a0, a1, a2, a3, aaddr);
#pragma unroll
                for (int ng = 0; ng < 2; ng++) {
                    const int nb0 = ng * 2;
                    const int boff = (ks * 16 + kB_row) * 136 + kB_col + ng * 16;
                    uint32_t b0, b1, b2, b3r;
                    uint32_t baddr = (uint32_t)__cvta_generic_to_shared(&whm[boff]);
                    ldsm4t(b0, b1, b2, b3r, baddr);
                    mma16816(acc[nb0],     a0, a1, a2, a3, b0, b1);
                    mma16816(acc[nb0 + 1], a0, a1, a2, a3, b2, b3r);
                }
            }
        }

        // ---- e-phase(jt): p = ex2(max(A+t', fma(0.2,t',B))), bit-masked ----
        {
            float* tvb = tv + b3 * JW;
            const unsigned mbyte = (bw_cur >> ((ej & 3) * 8)) & 0xffu;
            float4 t0 = *(float4*)&tvb[ej * 8];
            float4 t1 = *(float4*)&tvb[ej * 8 + 4];
            float tt[8] = {t0.x, t0.y, t0.z, t0.w, t1.x, t1.y, t1.z, t1.w};
            uint32_t pk[4];
#pragma unroll
            for (int d = 0; d < 4; d++) {
                float ta = tt[2 * d], tb = tt[2 * d + 1];
                float e0 = fmaxf(A + ta, fmaf(GAT_ALPHA, ta, B));
                float e1 = fmaxf(A + tb, fmaf(GAT_ALPHA, tb, B));
                e0 = ((mbyte >> (2 * d)) & 1u) ? e0 : -INFINITY;
                e1 = ((mbyte >> (2 * d + 1)) & 1u) ? e1 : -INFINITY;
                float p0 = ex2(e0), p1 = ex2(e1);
                l_acc += p0 + p1;
                ((__half2*)pk)[d] = __floats2half2_rn(p0, p1);
            }
            *(uint4*)&Psb[er * 72 + ej * 8] = *(uint4*)&pk[0];
        }
        bw_cur = bw_nxt;
        b3 = bn;
    }

    // ---- final MMA(NTJ-1) ----
    __syncthreads();
    {
        __half* Psm = Ps + ((NTJ - 1) & 1) * 32 * 72;
        __half* whm = whh + ((NTJ - 1) % 3) * JW * 136;
#pragma unroll
        for (int ks = 0; ks < 4; ks++) {
            uint32_t a0, a1, a2, a3;
            uint32_t aaddr = (uint32_t)__cvta_generic_to_shared(
                &Psm[kA_row * 72 + ks * 16 + (lane >> 4) * 8]);
            ldsm4(a0, a1, a2, a3, aaddr);
#pragma unroll
            for (int ng = 0; ng < 2; ng++) {
                const int nb0 = ng * 2;
                const int boff = (ks * 16 + kB_row) * 136 + kB_col + ng * 16;
                uint32_t b0, b1, b2, b3r;
                uint32_t baddr = (uint32_t)__cvta_generic_to_shared(&whm[boff]);
                ldsm4t(b0, b1, b2, b3r, baddr);
                mma16816(acc[nb0],     a0, a1, a2, a3, b0, b1);
                mma16816(acc[nb0 + 1], a0, a1, a2, a3, b2, b3r);
            }
        }
    }

    // ---- final l reduction (8 threads/row, same warp) ----
    l_acc += __shfl_xor_sync(0xffffffffu, l_acc, 1);
    l_acc += __shfl_xor_sync(0xffffffffu, l_acc, 2);
    l_acc += __shfl_xor_sync(0xffffffffu, l_acc, 4);
    __syncthreads();
    if (ej == 0) linv[er] = 1.0f / l_acc;
    __syncthreads();

    // ---- epilogue: normalize, ELU, store ----
    const float li_lo = linv[wm * 16 + (lane >> 2)];
    const float li_hi = linv[wm * 16 + 8 + (lane >> 2)];
    const int rg0 = i0 + wm * 16 + (lane >> 2);
#pragma unroll
    for (int nb = 0; nb < 4; nb++) {
        const int col = wn * 32 + nb * 8 + (lane & 3) * 2;
        float v0 = acc[nb][0] * li_lo, v1 = acc[nb][1] * li_lo;
        float v2 = acc[nb][2] * li_hi, v3 = acc[nb][3] * li_hi;
        v0 = (v0 > 0.f) ? v0 : expm1f(v0);
        v1 = (v1 > 0.f) ? v1 : expm1f(v1);
        v2 = (v2 > 0.f) ? v2 : expm1f(v2);
        v3 = (v3 > 0.f) ? v3 : expm1f(v3);
        out[(size_t)rg0 * FOUT + col]           = v0;
        out[(size_t)rg0 * FOUT + col + 1]       = v1;
        out[(size_t)(rg0 + 8) * FOUT + col]     = v2;
        out[(size_t)(rg0 + 8) * FOUT + col + 1] = v3;
    }
}

// ---------------- launch ----------------
extern "C" void kernel_launch(void* const* d_in, const int* in_sizes, int n_in,
                              void* d_out, int out_size)
{
    const float* h = nullptr;
    const int*   adj = nullptr;
    const float* W = nullptr;
    const float* a = nullptr;
    for (int i = 0; i < n_in; i++) {
        long s = in_sizes[i];
        if (s == (long)NN * FIN)        h   = (const float*)d_in[i];
        else if (s == (long)NN * NN)    adj = (const int*)d_in[i];
        else if (s == (long)FIN * FOUT) W   = (const float*)d_in[i];
        else if (s == 2 * FOUT)         a   = (const float*)d_in[i];
    }
    float* out = (float*)d_out;

    cudaFuncSetAttribute(attn_kernel,
                         cudaFuncAttributeMaxDynamicSharedMemorySize, SMEM_BYTES);

    pack_kernel<<<NN * NN / 2048, 256>>>(adj);
    wh_kernel<<<NN / 64, 256>>>(h, W, a);
    attn_kernel<<<NN / 32, 256, SMEM_BYTES>>>(out);
}